// round 11
// baseline (speedup 1.0000x reference)
#include <cuda_runtime.h>

#define T_DATA 20000
#define TOFF   256
#define NXI    20400   // g_INT2 rows: TOFF + 20000 + pad (pad only read for discarded outputs)
#define TILE   136     // outputs (and pack rows) per block; 148*136 = 20128 >= 20000
#define NBLK   148
#define NTHR   768

// ---------------- device scratch ----------------
__device__ float2   g_INT2[NXI * 12];    // [x][s] = (IN_e, IN_i), x = TOFF + t
__device__ float4   g_KER4[12 * 200];    // (kes, kis, ken, kin) per (s,k)
__device__ unsigned g_bar_count;         // zero-init; self-resetting
__device__ unsigned g_bar_gen;           // monotone generation

__device__ __forceinline__ float sigmoidf_(float x) {
    return 1.0f / (1.0f + __expf(-x));
}

// packed f32x2 helpers (Blackwell)
#define FMA2(acc, a, b) \
    asm("fma.rn.f32x2 %0, %1, %2, %3;" : "=l"(acc) : "l"(a), "l"(b), "l"(acc))
#define PACK2(out, lo, hi) \
    asm("mov.b64 %0, {%1, %2};" : "=l"(out) : "f"(lo), "f"(hi))
#define UNPACK2(lo, hi, in) \
    asm("mov.b64 {%0, %1}, %2;" : "=f"(lo), "=f"(hi) : "l"(in))

__device__ __forceinline__ float coef1(const float* __restrict__ W,
                                       const float* __restrict__ D,
                                       int s, int c, float t) {
    float ts = fmaxf(t - expf(D[s * 2 + c]), 0.f);
    float acc = 0.f;
    #pragma unroll
    for (int b = 0; b < 3; ++b) {
        float tau = expf(0.5f * (float)b);
        float tt  = ts / tau;
        acc += W[s * 6 + b * 2 + c] * tt * expf(-tt);
    }
    return acc;
}

// smem layout for phase B (floats within buf)
#define SS_OFF   0        // float [12*148] syn_s
#define SNS_OFF  1776     // float [12*148] syn_ns
#define XNO_OFF  3552     // float [12*148] cascade levels
#define SOUT_OFF 5328     // float [136*35]
#define BUFSZ    10088    // sIN (348*12 float2 = 8352 floats) aliases offset 0

// ================= single persistent kernel =================
__global__ void __launch_bounds__(NTHR, 1)
mega(const float4* __restrict__ Se4, const float4* __restrict__ Si4,
     const float4* __restrict__ Ce4, const float4* __restrict__ Ci4,
     const float* __restrict__ Cden,
     const float* __restrict__ Wss,  const float* __restrict__ Wns,
     const float* __restrict__ Dss,  const float* __restrict__ Dns,
     const float* __restrict__ Ths,  const float* __restrict__ Thns,
     const float* __restrict__ Wssub, const float* __restrict__ Wnssub,
     float* __restrict__ out) {
    __shared__ __align__(16) float buf[BUFSZ];
    __shared__ unsigned sCE[768], sCI[192];
    __shared__ float cwns[144], cds[144];
    __shared__ float ths[12], thns[12], ws[12], wns[12];

    int tid  = threadIdx.x;
    int warp = tid >> 5, lane = tid & 31;
    int bid  = blockIdx.x;
    int t0   = bid * TILE;
    const float4 z4 = make_float4(0.f, 0.f, 0.f, 0.f);

    // ---- phase 0: per-block mask tables (ballot pack of C), params, side prep ----
    #pragma unroll
    for (int gw = warp; gw < 240; gw += 24) {
        if (gw < 192) {                               // E: 16 chunks x 12 subunits
            int w = gw / 12, s = gw % 12;
            int f = w * 32 + lane;
            float4 v = (f < 500) ? __ldg(Ce4 + s * 500 + f) : z4;
            unsigned m0 = __ballot_sync(0xffffffffu, v.x != 0.f);
            unsigned m1 = __ballot_sync(0xffffffffu, v.y != 0.f);
            unsigned m2 = __ballot_sync(0xffffffffu, v.z != 0.f);
            unsigned m3 = __ballot_sync(0xffffffffu, v.w != 0.f);
            if (lane == 0) {
                sCE[(4 * w + 0) * 12 + s] = m0;
                sCE[(4 * w + 1) * 12 + s] = m1;
                sCE[(4 * w + 2) * 12 + s] = m2;
                sCE[(4 * w + 3) * 12 + s] = m3;
            }
        } else {                                      // I: 4 chunks x 12 subunits
            int j = gw - 192;
            int w = j / 12, s = j % 12;
            int f = w * 32 + lane;
            float4 v = (f < 125) ? __ldg(Ci4 + s * 125 + f) : z4;
            unsigned m0 = __ballot_sync(0xffffffffu, v.x != 0.f);
            unsigned m1 = __ballot_sync(0xffffffffu, v.y != 0.f);
            unsigned m2 = __ballot_sync(0xffffffffu, v.z != 0.f);
            unsigned m3 = __ballot_sync(0xffffffffu, v.w != 0.f);
            if (lane == 0) {
                sCI[(4 * w + 0) * 12 + s] = m0;
                sCI[(4 * w + 1) * 12 + s] = m1;
                sCI[(4 * w + 2) * 12 + s] = m2;
                sCI[(4 * w + 3) * 12 + s] = m3;
            }
        }
    }
    if (tid < 144) {
        float c = Cden[tid];
        cds [tid] = c;
        cwns[tid] = c * Wnssub[tid % 12];
    }
    if (tid >= 160 && tid < 172) {
        int q = tid - 160;
        ths [q] = Ths[q];
        thns[q] = Thns[q];
        ws  [q] = Wssub[q];
        wns [q] = Wnssub[q];
    }
    if (bid == 0) {                                   // zero t<0 pad of g_INT2
        for (int i = tid; i < TOFF * 12; i += NTHR)
            g_INT2[i] = make_float2(0.f, 0.f);
    } else if (bid == 1) {                            // synaptic kernel coefficients
        for (int gid = tid; gid < 2400; gid += NTHR) {
            int s = gid / 200, k = gid % 200;
            float t = (float)k;
            float4 o;
            o.x = coef1(Wss, Dss, s, 0, t);
            o.y = coef1(Wss, Dss, s, 1, t);
            o.z = coef1(Wns, Dns, s, 0, t);
            o.w = coef1(Wns, Dns, s, 1, t);
            g_KER4[gid] = o;
        }
    }
    __syncthreads();

    // ---- phase A: pack + popcount GEMM for rows [t0, t0+TILE) ----
    {
        int lc = (lane < 12) ? lane : 0;
        for (int r = warp; r < TILE; r += 24) {       // warp-uniform row
            int row = t0 + r;
            if (row >= T_DATA) break;
            const float4* rE = Se4 + (size_t)row * 500;
            const float4* rI = Si4 + (size_t)row * 125;
            int accE = 0, accI = 0;
            float4 vb[4];
            #pragma unroll
            for (int j = 0; j < 4; ++j) vb[j] = __ldg(rE + j * 32 + lane);
            #pragma unroll
            for (int w = 0; w < 16; ++w) {
                float4 v = vb[w & 3];
                int wn = w + 4;
                if (wn < 16) {
                    int f = wn * 32 + lane;
                    vb[w & 3] = (f < 500) ? __ldg(rE + f) : z4;
                } else {
                    int f = (wn - 16) * 32 + lane;
                    vb[w & 3] = (f < 125) ? __ldg(rI + f) : z4;
                }
                unsigned m0 = __ballot_sync(0xffffffffu, v.x != 0.f);
                unsigned m1 = __ballot_sync(0xffffffffu, v.y != 0.f);
                unsigned m2 = __ballot_sync(0xffffffffu, v.z != 0.f);
                unsigned m3 = __ballot_sync(0xffffffffu, v.w != 0.f);
                int bb = w * 48 + lc;
                accE += __popc(m0 & sCE[bb]);
                accE += __popc(m1 & sCE[bb + 12]);
                accE += __popc(m2 & sCE[bb + 24]);
                accE += __popc(m3 & sCE[bb + 36]);
            }
            #pragma unroll
            for (int w = 0; w < 4; ++w) {
                float4 v = vb[w];
                unsigned m0 = __ballot_sync(0xffffffffu, v.x != 0.f);
                unsigned m1 = __ballot_sync(0xffffffffu, v.y != 0.f);
                unsigned m2 = __ballot_sync(0xffffffffu, v.z != 0.f);
                unsigned m3 = __ballot_sync(0xffffffffu, v.w != 0.f);
                int bb = w * 48 + lc;
                accI += __popc(m0 & sCI[bb]);
                accI += __popc(m1 & sCI[bb + 12]);
                accI += __popc(m2 & sCI[bb + 24]);
                accI += __popc(m3 & sCI[bb + 36]);
            }
            if (lane < 12)
                g_INT2[(TOFF + row) * 12 + lane] =
                    make_float2((float)accE, (float)accI);
        }
    }

    // ---- grid barrier (all 148 CTAs co-resident: grid <= SM count) ----
    __threadfence();
    __syncthreads();
    if (tid == 0) {
        unsigned gen = atomicAdd(&g_bar_gen, 0u);     // read before arriving
        unsigned old = atomicAdd(&g_bar_count, 1u);
        if (old == NBLK - 1) {
            atomicExch(&g_bar_count, 0u);             // self-reset for replay
            __threadfence();
            atomicAdd(&g_bar_gen, 1u);                // release
        } else {
            while (atomicAdd(&g_bar_gen, 0u) == gen) __nanosleep(64);
            __threadfence();
        }
    }
    __syncthreads();

    // ---- phase B: conv (sliding window + f32x2) + cascade + output ----
    // stage IN window: sIN[s][xx] = IN at t = t0 - 212 + xx, xx in [0,348)
    float2* sIN = (float2*)buf;                       // [s][xx], pitch 348
    {
        int base = (TOFF + t0 - 212) * 12;
        for (int i = tid; i < 4176; i += NTHR) {      // 348 * 12, coalesced
            int xx = i / 12, s = i % 12;
            sIN[s * 348 + xx] = g_INT2[base + i];
        }
    }
    __syncthreads();

    if (warp < 12) {                                  // conv: warp = subunit
        int s = warp;
        int mbase = 5 * lane;
        const unsigned long long* row =
            (const unsigned long long*)(sIN + s * 348);
        unsigned long long W0, W1, W2, W3, W4;
        unsigned long long aS0 = 0, aS1 = 0, aS2 = 0, aS3 = 0, aS4 = 0;
        unsigned long long aN0 = 0, aN1 = 0, aN2 = 0, aN3 = 0, aN4 = 0;
        W0 = row[min(mbase + 200, 347)];
        W1 = row[min(mbase + 201, 347)];
        W2 = row[min(mbase + 202, 347)];
        W3 = row[min(mbase + 203, 347)];
        W4 = row[min(mbase + 204, 347)];
        const float4* kp = g_KER4 + s * 200;
        #pragma unroll 5
        for (int k = 0; k < 200; ++k) {
            float4 kc = __ldg(kp + k);
            unsigned long long cs, cn;
            PACK2(cs, kc.x, kc.y);
            PACK2(cn, kc.z, kc.w);
            FMA2(aS0, W0, cs); FMA2(aN0, W0, cn);
            FMA2(aS1, W1, cs); FMA2(aN1, W1, cn);
            FMA2(aS2, W2, cs); FMA2(aN2, W2, cn);
            FMA2(aS3, W3, cs); FMA2(aN3, W3, cn);
            FMA2(aS4, W4, cs); FMA2(aN4, W4, cn);
            W4 = W3; W3 = W2; W2 = W1; W1 = W0;
            W0 = row[min(mbase + 199 - k, 347)];
        }
        __syncthreads();                              // sIN dead; buf reusable
        float lo, hi;
        #pragma unroll
        for (int j = 0; j < 5; ++j) {
            int m = mbase + j;
            if (m < 148) {
                unsigned long long vS, vN;
                switch (j) {
                    case 0: vS = aS0; vN = aN0; break;
                    case 1: vS = aS1; vN = aN1; break;
                    case 2: vS = aS2; vN = aN2; break;
                    case 3: vS = aS3; vN = aN3; break;
                    default: vS = aS4; vN = aN4; break;
                }
                UNPACK2(lo, hi, vS); buf[SS_OFF  + s * 148 + m] = lo + hi;
                UNPACK2(lo, hi, vN); buf[SNS_OFF + s * 148 + m] = lo + hi;
            }
        }
    } else {
        __syncthreads();                              // match conv's barrier
    }
    __syncthreads();

    // cascade: 12 lower-triangular levels over cols m = 0..147
    #pragma unroll
    for (int i = 0; i < 12; ++i) {
        if (tid < 148) {
            int t = t0 - 12 + tid;
            float v = 0.f;
            if (t >= 0) {
                float x = buf[SNS_OFF + i * 148 + tid] + thns[i];
                #pragma unroll
                for (int j = 0; j < i; ++j) {
                    float yp = (tid > 0) ? buf[XNO_OFF + j * 148 + tid - 1] : 0.f;
                    x = fmaf(cwns[i * 12 + j], yp, x);
                }
                v = sigmoidf_(x);
            }
            buf[XNO_OFF + i * 148 + tid] = v;
        }
        __syncthreads();
    }

    // epilogue: per-t outputs
    if (tid < TILE) {
        int t = t0 + tid, h = tid + 12;
        if (t < T_DATA) {
            float ysp[12];
            if (t == 0) {
                #pragma unroll
                for (int j = 0; j < 12; ++j) ysp[j] = 0.f;
            } else {
                float x0 = buf[SS_OFF + 0 * 148 + tid + 11] + ths[0];
                ysp[0] = sigmoidf_(x0) * ws[0];
                #pragma unroll
                for (int j = 1; j < 12; ++j)
                    ysp[j] = buf[XNO_OFF + j * 148 + h - 1] * ws[j];
            }
            float* o = buf + SOUT_OFF + tid * 35;
            #pragma unroll
            for (int i = 0; i < 12; ++i) {
                float xs = buf[SS_OFF + i * 148 + tid + 12] + ths[i];
                #pragma unroll
                for (int j = 0; j < i; ++j) xs = fmaf(cds[i * 12 + j], ysp[j], xs);
                float sg  = sigmoidf_(xs);
                float xti = buf[XNO_OFF + i * 148 + h];
                o[i]      = (i == 0) ? sg * ws[0] : xti * ws[i];
                o[12 + i] = xti * wns[i];
                if (i >= 1) o[24 + i - 1] = sg;
            }
        }
    }
    __syncthreads();
    int nvalid = T_DATA - t0; if (nvalid > TILE) nvalid = TILE;
    float* ob = out + (size_t)t0 * 35;
    if (nvalid == TILE) {
        float4* o4 = (float4*)ob;                     // t0*35 % 4 == 0
        const float4* sb = (const float4*)(buf + SOUT_OFF);
        for (int i = tid; i < 1190; i += NTHR) o4[i] = sb[i];
    } else if (nvalid > 0) {
        int nf = nvalid * 35;
        for (int i = tid; i < nf; i += NTHR) ob[i] = buf[SOUT_OFF + i];
    }
}

// ---------------- launch ----------------
extern "C" void kernel_launch(void* const* d_in, const int* in_sizes, int n_in,
                              void* d_out, int out_size) {
    const float* S_e      = (const float*)d_in[0];
    const float* S_i      = (const float*)d_in[1];
    const float* C_syn_e  = (const float*)d_in[2];
    const float* C_syn_i  = (const float*)d_in[3];
    const float* C_den    = (const float*)d_in[4];
    const float* W_s_syn  = (const float*)d_in[5];
    const float* W_ns_syn = (const float*)d_in[6];
    const float* D_s      = (const float*)d_in[7];
    const float* D_ns     = (const float*)d_in[8];
    const float* Theta_s  = (const float*)d_in[9];
    const float* Theta_ns = (const float*)d_in[10];
    const float* W_s_sub  = (const float*)d_in[11];
    const float* W_ns_sub = (const float*)d_in[12];
    float* out = (float*)d_out;

    mega<<<NBLK, NTHR>>>((const float4*)S_e, (const float4*)S_i,
                         (const float4*)C_syn_e, (const float4*)C_syn_i,
                         C_den, W_s_syn, W_ns_syn, D_s, D_ns,
                         Theta_s, Theta_ns, W_s_sub, W_ns_sub, out);
}